// round 16
// baseline (speedup 1.0000x reference)
#include <cuda_runtime.h>
#include <cuda_bf16.h>
#include <math.h>
#include <stdint.h>

// ---------------- Problem constants ----------------
#define BATCH  2
#define SEQ    2048
#define DMODEL 1024
#define NHEAD  16
#define DK     64
#define MROWS  4096        // BATCH*SEQ
#define KDIM   1024
#define KC_COUNT 16        // KDIM / 64

// Feature gate: tcgen05 exists only in the arch-specific target.
#if defined(__CUDA_ARCH_FEAT_SM103_ALL) || defined(__CUDA_ARCH_FEAT_SM100_ALL) || defined(__CUDA_ARCH_FEAT_SM101_ALL)
#define HAS_TC 1
#else
#define HAS_TC 0
#endif

// ---------------- Scratch (device globals; allocations forbidden) ----------
#define OFF_Q   0
#define OFF_K   4194304
#define OFF_V   8388608
#define OFF_CTX 12582912
#define OFF_WQ  16777216
#define OFF_WK  17825792
#define OFF_WV  18874368
#define OFF_WO  19922944
__device__ __nv_bfloat16 g_hi[20971520];
__device__ __nv_bfloat16 g_lo[20971520];

// Attention operand tiles (written by projection GEMM epilogues):
// Q,K: per (bh, stile) [128 seq x 64 dk] bf16 SW128 tiles (16KB each).
// V:   per (bh, stile) transposed [64 dk x 128 keys] blocked-atom SW128 tiles.
__device__ __align__(1024) __nv_bfloat16 g_tqh[4194304];
__device__ __align__(1024) __nv_bfloat16 g_tql[4194304];
__device__ __align__(1024) __nv_bfloat16 g_tkh[4194304];
__device__ __align__(1024) __nv_bfloat16 g_tkl[4194304];
__device__ __align__(1024) __nv_bfloat16 g_tvh[4194304];
__device__ __align__(1024) __nv_bfloat16 g_tvl[4194304];

// ---------------- PTX helpers ----------------
__device__ __forceinline__ uint32_t smem_u32(const void* p) {
    uint32_t a;
    asm("{ .reg .u64 t; cvta.to.shared.u64 t, %1; cvt.u32.u64 %0, t; }" : "=r"(a) : "l"(p));
    return a;
}

#define SWZ128(o) ((o) ^ (((o) >> 3) & 0x70))

#define MBARRIER_INIT(addr, cnt) \
    asm volatile("mbarrier.init.shared.b64 [%0], %1;" :: "r"(addr), "r"(cnt) : "memory")

#define MBARRIER_EXPECT_TX(addr, bytes) \
    asm volatile("mbarrier.arrive.expect_tx.shared.b64 _, [%0], %1;" :: "r"(addr), "r"(bytes) : "memory")

#define MBARRIER_WAIT_PARITY(addr, par) do {                                  \
    uint32_t _m = (addr); uint32_t _p = (par); uint32_t _d;                   \
    asm volatile("{\n\t.reg .pred p;\n\t"                                     \
        "mbarrier.try_wait.parity.acquire.cta.shared::cta.b64 p, [%1], %2;\n\t"\
        "selp.b32 %0, 1, 0, p;\n\t}" : "=r"(_d) : "r"(_m), "r"(_p) : "memory");\
    if (!_d) {                                                                \
        asm volatile("{\n\t.reg .pred P1;\n\t"                                \
        "W_%=:\n\t"                                                           \
        "mbarrier.try_wait.parity.acquire.cta.shared::cta.b64 P1, [%0], %1, 0x989680;\n\t" \
        "@P1 bra.uni D_%=;\n\t"                                               \
        "bra.uni W_%=;\n\t"                                                   \
        "D_%=:\n\t}" :: "r"(_m), "r"(_p) : "memory");                         \
    }                                                                         \
} while (0)

#define BULK_G2S(dst, src, bytes, mbar) \
    asm volatile("cp.async.bulk.shared::cluster.global.mbarrier::complete_tx::bytes [%0], [%1], %2, [%3];" \
        :: "r"(dst), "l"(src), "r"(bytes), "r"(mbar) : "memory")

#define TCGEN05_ALLOC(saddr, ncols) \
    asm volatile("tcgen05.alloc.cta_group::1.sync.aligned.shared::cta.b32 [%0], %1;" \
        :: "r"(saddr), "r"(ncols) : "memory")
#define TCGEN05_DEALLOC(tmem, ncols) \
    asm volatile("tcgen05.dealloc.cta_group::1.sync.aligned.b32 %0, %1;" :: "r"(tmem), "r"(ncols))
#define TCGEN05_RELINQ() \
    asm volatile("tcgen05.relinquish_alloc_permit.cta_group::1.sync.aligned;")
#define TCGEN05_COMMIT(mbar) \
    asm volatile("tcgen05.commit.cta_group::1.mbarrier::arrive::one.shared::cluster.b64 [%0];" \
        :: "r"(mbar) : "memory")
#define TCGEN05_FENCE_AFTER()  asm volatile("tcgen05.fence::after_thread_sync;" ::: "memory")
#define TCGEN05_FENCE_BEFORE() asm volatile("tcgen05.fence::before_thread_sync;" ::: "memory")
#define TCGEN05_WAIT_LD()      asm volatile("tcgen05.wait::ld.sync.aligned;" ::: "memory")
#define TCGEN05_WAIT_ST()      asm volatile("tcgen05.wait::st.sync.aligned;" ::: "memory")
#define FENCE_PROXY_ASYNC()    asm volatile("fence.proxy.async.shared::cta;" ::: "memory")

#define TCGEN05_LD_X32(r, taddr) \
    asm volatile("tcgen05.ld.sync.aligned.32x32b.x32.b32 " \
        "{%0, %1, %2, %3, %4, %5, %6, %7, %8, %9, %10, %11, %12, %13, %14, %15, " \
        " %16, %17, %18, %19, %20, %21, %22, %23, %24, %25, %26, %27, %28, %29, %30, %31}, [%32];" \
        : "=r"((r)[0]), "=r"((r)[1]), "=r"((r)[2]), "=r"((r)[3]), \
          "=r"((r)[4]), "=r"((r)[5]), "=r"((r)[6]), "=r"((r)[7]), \
          "=r"((r)[8]), "=r"((r)[9]), "=r"((r)[10]), "=r"((r)[11]), \
          "=r"((r)[12]), "=r"((r)[13]), "=r"((r)[14]), "=r"((r)[15]), \
          "=r"((r)[16]), "=r"((r)[17]), "=r"((r)[18]), "=r"((r)[19]), \
          "=r"((r)[20]), "=r"((r)[21]), "=r"((r)[22]), "=r"((r)[23]), \
          "=r"((r)[24]), "=r"((r)[25]), "=r"((r)[26]), "=r"((r)[27]), \
          "=r"((r)[28]), "=r"((r)[29]), "=r"((r)[30]), "=r"((r)[31]) \
        : "r"(taddr))

#define TCGEN05_LD_X16(r, taddr) \
    asm volatile("tcgen05.ld.sync.aligned.32x32b.x16.b32 " \
        "{%0, %1, %2, %3, %4, %5, %6, %7, %8, %9, %10, %11, %12, %13, %14, %15}, [%16];" \
        : "=r"((r)[0]), "=r"((r)[1]), "=r"((r)[2]), "=r"((r)[3]), \
          "=r"((r)[4]), "=r"((r)[5]), "=r"((r)[6]), "=r"((r)[7]), \
          "=r"((r)[8]), "=r"((r)[9]), "=r"((r)[10]), "=r"((r)[11]), \
          "=r"((r)[12]), "=r"((r)[13]), "=r"((r)[14]), "=r"((r)[15]) \
        : "r"(taddr))

#define TCGEN05_ST_X16(taddr, r) \
    asm volatile("tcgen05.st.sync.aligned.32x32b.x16.b32 [%0], " \
        "{%1, %2, %3, %4, %5, %6, %7, %8, %9, %10, %11, %12, %13, %14, %15, %16};" \
        :: "r"(taddr), \
           "r"((r)[0]), "r"((r)[1]), "r"((r)[2]), "r"((r)[3]), \
           "r"((r)[4]), "r"((r)[5]), "r"((r)[6]), "r"((r)[7]), \
           "r"((r)[8]), "r"((r)[9]), "r"((r)[10]), "r"((r)[11]), \
           "r"((r)[12]), "r"((r)[13]), "r"((r)[14]), "r"((r)[15]) \
        : "memory")

// SMEM descriptor: SW128, version=1, SBO=64, LBO=1 (K-major bf16, 128B rows)
#define SMEM_DESC_BASE ((uint64_t(2) << 61) | (uint64_t(1) << 46) | (uint64_t(64) << 32) | (uint64_t(1) << 16))
#define MAKE_DESC(a) (SMEM_DESC_BASE | ((uint64_t)((a) >> 4) & 0x3FFF))

#define IDESC_N128 0x08200490u   // M=128, N=128
#define IDESC_N64  0x08100490u   // M=128, N=64

__device__ __forceinline__ void mma_ss(uint32_t d_tmem, uint64_t a_desc, uint64_t b_desc,
                                       uint32_t idesc, bool acc) {
#if HAS_TC
    uint32_t en = acc ? 1u : 0u;
    asm volatile(
        "{\n\t.reg .pred p;\n\t"
        "setp.ne.u32 p, %4, 0;\n\t"
        "tcgen05.mma.cta_group::1.kind::f16 [%0], %1, %2, %3, p;\n\t}"
        :: "r"(d_tmem), "l"(a_desc), "l"(b_desc), "r"(idesc), "r"(en) : "memory");
#endif
}
__device__ __forceinline__ void mma_ts(uint32_t d_tmem, uint32_t a_tmem, uint64_t b_desc,
                                       uint32_t idesc, bool acc) {
#if HAS_TC
    uint32_t en = acc ? 1u : 0u;
    asm volatile(
        "{\n\t.reg .pred p;\n\t"
        "setp.ne.u32 p, %4, 0;\n\t"
        "tcgen05.mma.cta_group::1.kind::f16 [%0], [%1], %2, %3, p;\n\t}"
        :: "r"(d_tmem), "r"(a_tmem), "l"(b_desc), "r"(idesc), "r"(en) : "memory");
#endif
}

__device__ __forceinline__ float ex2f(float x) {
    float y;
    asm("ex2.approx.f32 %0, %1;" : "=f"(y) : "f"(x));
    return y;
}
// Split two fp32 into packed bf16 hi + packed bf16 residual lo (rn rounding).
__device__ __forceinline__ void split2(float x, float y, uint32_t& h, uint32_t& l) {
    asm("cvt.rn.bf16x2.f32 %0, %1, %2;" : "=r"(h) : "f"(y), "f"(x));
    float hx = __uint_as_float(h << 16);
    float hy = __uint_as_float(h & 0xffff0000u);
    asm("cvt.rn.bf16x2.f32 %0, %1, %2;" : "=r"(l) : "f"(y - hy), "f"(x - hx));
}

// ---------------- Converter: 8 elems/thread, single merged launch -----------
__device__ __forceinline__ void convert_body8(const float* __restrict__ src,
                                              __nv_bfloat16* __restrict__ hi,
                                              __nv_bfloat16* __restrict__ lo, int mtiles) {
#if HAS_TC
    int idx = blockIdx.x * 256 + threadIdx.x;   // chunk index: m*128 + ck
    int m  = idx >> 7;
    int ck = idx & 127;
    int kc = ck >> 3;
    int r  = m & 127, mt = m >> 7;
    uint32_t off = SWZ128((uint32_t)(r * 128 + (ck & 7) * 16));
    size_t base = ((size_t)(kc * mtiles + mt) << 14) + off;

    const float4* s4 = reinterpret_cast<const float4*>(src + (size_t)m * KDIM + ck * 8);
    float4 a = s4[0], b = s4[1];
    uint4 hq, lq;
    split2(a.x, a.y, hq.x, lq.x);
    split2(a.z, a.w, hq.y, lq.y);
    split2(b.x, b.y, hq.z, lq.z);
    split2(b.z, b.w, hq.w, lq.w);
    *reinterpret_cast<uint4*>(reinterpret_cast<char*>(hi) + base) = hq;
    *reinterpret_cast<uint4*>(reinterpret_cast<char*>(lo) + base) = lq;
#endif
}

__global__ void __launch_bounds__(256)
convert_all(const float* __restrict__ q, const float* __restrict__ k,
            const float* __restrict__ v, const float* __restrict__ wq,
            const float* __restrict__ wk, const float* __restrict__ wv,
            const float* __restrict__ wo) {
#if HAS_TC
    const int z = blockIdx.z;
    if (z < 3) {
        const float* src = (z == 0) ? q : (z == 1) ? k : v;
        size_t off = (z == 0) ? OFF_Q : (z == 1) ? OFF_K : OFF_V;
        convert_body8(src, g_hi + off, g_lo + off, 32);
    } else {
        if (blockIdx.x >= 512) return;   // weights: 1024x1024 only
        const float* src = (z == 3) ? wq : (z == 4) ? wk : (z == 5) ? wv : wo;
        size_t off = (z == 3) ? OFF_WQ : (z == 4) ? OFF_WK : (z == 5) ? OFF_WV : OFF_WO;
        convert_body8(src, g_hi + off, g_lo + off, 8);
    }
#endif
}

// ---------------- tcgen05 split-bf16 GEMM v4: 128x128 tiles, 2 CTAs/SM ------
// Chunk c (0..31): kc = c>>1, part = c&1 (0: A-hi+B-hi, 1: A-lo+B-lo).
// Slot s = c%3 holds A-part (16KB) + B-part (16KB) = 32KB. smem = 99KB ->
// 2 CTAs/SM co-residency (the R12 lever) hides the exposed TMA latency that
// pinned the 1-CTA/SM version at 2x its MMA floor.
#define TILE_B   16384
#define SM_CTRL  0
#define SM_FULL(s)  (16 + (s) * 8)
#define SM_EMPTY(s) (48 + (s) * 8)
#define SM_DONE  80
#define GC_SLOT_B 32768
#define SM_A(s) (1024 + (s) * GC_SLOT_B)
#define SM_B(s) (SM_A(s) + 16384)
#define GEMM_SMEM (1024 + 3 * GC_SLOT_B)   // 99328

__device__ __forceinline__ void
gemm_body(const __nv_bfloat16* __restrict__ ahi, const __nv_bfloat16* __restrict__ alo,
          const __nv_bfloat16* __restrict__ bhi, const __nv_bfloat16* __restrict__ blo,
          float* __restrict__ outflat, int dst, int mtilesA) {
#if HAS_TC
    extern __shared__ char smem[];
    const uint32_t sb = smem_u32(smem);
    const int tid = threadIdx.x, wid = tid >> 5, lid = tid & 31;
    const int mt = blockIdx.y, nt = blockIdx.x;

    if (tid == 0) {
        #pragma unroll
        for (int s = 0; s < 3; s++) {
            MBARRIER_INIT(sb + SM_FULL(s), 1);
            MBARRIER_INIT(sb + SM_EMPTY(s), 1);
        }
        MBARRIER_INIT(sb + SM_DONE, 1);
        FENCE_PROXY_ASYNC();
    }
    if (wid == 0) {
        TCGEN05_ALLOC(sb + SM_CTRL, 128);
        TCGEN05_RELINQ();   // release permit -> co-resident CTA can alloc
    }
    __syncthreads();

    uint32_t tmem;
    asm volatile("ld.shared.b32 %0, [%1];" : "=r"(tmem) : "r"(sb + SM_CTRL));

    if (tid == 32) {
        // Producer: 32 half-chunks of 32KB.
        int ph[3] = {1, 1, 1};
        for (int c = 0; c < 32; c++) {
            const int s = c % 3, kc = c >> 1, part = c & 1;
            MBARRIER_WAIT_PARITY(sb + SM_EMPTY(s), ph[s]); ph[s] ^= 1;
            MBARRIER_EXPECT_TX(sb + SM_FULL(s), 2 * TILE_B);
            const char* asrc = (const char*)(part ? alo : ahi) +
                               ((size_t)(kc * mtilesA + mt) << 14);
            const char* bsrc = (const char*)(part ? blo : bhi) +
                               ((size_t)(kc * 8 + nt) << 14);
            BULK_G2S(sb + SM_A(s), asrc, TILE_B, sb + SM_FULL(s));
            BULK_G2S(sb + SM_B(s), bsrc, TILE_B, sb + SM_FULL(s));
        }
    } else if (tid == 0) {
        // Consumer.
        int fp[3] = {0, 0, 0};
        for (int c = 0; c < 32; c++) {
            const int s = c % 3;
            MBARRIER_WAIT_PARITY(sb + SM_FULL(s), fp[s]); fp[s] ^= 1;
            if ((c & 1) == 0) {
                // hi chunk: 4 MMAs A-hi * B-hi
                const uint64_t dah = MAKE_DESC(sb + SM_A(s));
                const uint64_t dbh = MAKE_DESC(sb + SM_B(s));
                #pragma unroll
                for (int ks = 0; ks < 4; ks++)
                    mma_ss(tmem, dah + ks * 2, dbh + ks * 2, IDESC_N128,
                           !(c == 0 && ks == 0));
            } else {
                // lo chunk: 8 MMAs cross terms (hi parts in slot (c-1)%3)
                const int sh = (c - 1) % 3;
                const uint64_t dah = MAKE_DESC(sb + SM_A(sh));
                const uint64_t dbh = MAKE_DESC(sb + SM_B(sh));
                const uint64_t dal = MAKE_DESC(sb + SM_A(s));
                const uint64_t dbl = MAKE_DESC(sb + SM_B(s));
                #pragma unroll
                for (int ks = 0; ks < 4; ks++) {
                    mma_ss(tmem, dah + ks * 2, dbl + ks * 2, IDESC_N128, true);
                    mma_ss(tmem, dal + ks * 2, dbh + ks * 2, IDESC_N128, true);
                }
                TCGEN05_COMMIT(sb + SM_EMPTY(sh));
                TCGEN05_COMMIT(sb + SM_EMPTY(s));
            }
        }
        TCGEN05_COMMIT(sb + SM_DONE);
    }

    MBARRIER_WAIT_PARITY(sb + SM_DONE, 0);
    TCGEN05_FENCE_AFTER();

    uint32_t d[64];
    const int colbase = (wid >> 2) * 64;
    TCGEN05_LD_X32(d, tmem + colbase);
    TCGEN05_LD_X32(d + 32, tmem + colbase + 32);
    TCGEN05_WAIT_LD();

    const int m = mt * 128 + (wid & 3) * 32 + lid;
    const int ng = nt * 128 + colbase;            // multiple of 64

    if (dst < 3) {
        const int b = m >> 11, sq = m & (SEQ - 1);
        const int h = ng >> 6;
        const int tile = (b * NHEAD + h) * 16 + (sq >> 7);
        const int rr = sq & 127;
        if (dst == 0 || dst == 1) {
            char* hb = (char*)(dst == 0 ? g_tqh : g_tkh) + ((size_t)tile << 14);
            char* lb = (char*)(dst == 0 ? g_tql : g_tkl) + ((size_t)tile << 14);
            #pragma unroll
            for (int c = 0; c < 64; c += 8) {
                uint4 hq, lq;
                split2(__uint_as_float(d[c + 0]), __uint_as_float(d[c + 1]), hq.x, lq.x);
                split2(__uint_as_float(d[c + 2]), __uint_as_float(d[c + 3]), hq.y, lq.y);
                split2(__uint_as_float(d[c + 4]), __uint_as_float(d[c + 5]), hq.z, lq.z);
                split2(__uint_as_float(d[c + 6]), __uint_as_float(d[c + 7]), hq.w, lq.w);
                uint32_t off = SWZ128((uint32_t)(rr * 128 + c * 2));
                *(uint4*)(hb + off) = hq;
                *(uint4*)(lb + off) = lq;
            }
        } else {
            char* hb = (char*)g_tvh + ((size_t)tile << 14);
            char* lb = (char*)g_tvl + ((size_t)tile << 14);
            const int kin = rr;
            #pragma unroll
            for (int c = 0; c < 64; c++) {
                float v0 = __uint_as_float(d[c]);
                __nv_bfloat16 h0 = __float2bfloat16(v0);
                __nv_bfloat16 l0 = __float2bfloat16(v0 - __bfloat162float(h0));
                uint32_t bo = (uint32_t)(((c >> 3) + (kin >> 6) * 8) * 1024 +
                                         (c & 7) * 128 + (kin & 63) * 2);
                uint32_t off = SWZ128(bo);
                *(__nv_bfloat16*)(hb + off) = h0;
                *(__nv_bfloat16*)(lb + off) = l0;
            }
        }
    } else {
        float* row = outflat + (size_t)m * DMODEL + ng;
        #pragma unroll
        for (int c = 0; c < 64; c += 4) {
            float4 v = make_float4(__uint_as_float(d[c]), __uint_as_float(d[c + 1]),
                                   __uint_as_float(d[c + 2]), __uint_as_float(d[c + 3]));
            *reinterpret_cast<float4*>(row + c) = v;
        }
    }
    TCGEN05_FENCE_BEFORE();

    __syncthreads();
    if (wid == 0) {
        TCGEN05_DEALLOC(tmem, 128);
    }
#endif
}

__global__ void __launch_bounds__(256, 2) gemm_qkv() {
#if HAS_TC
    const int z = blockIdx.z;
    const size_t aoff = (z == 0) ? OFF_Q : (z == 1) ? OFF_K : OFF_V;
    const size_t boff = (z == 0) ? OFF_WQ : (z == 1) ? OFF_WK : OFF_WV;
    gemm_body(g_hi + aoff, g_lo + aoff, g_hi + boff, g_lo + boff, nullptr, z, 32);
#endif
}

__global__ void __launch_bounds__(256, 2) gemm_wo(float* __restrict__ out) {
#if HAS_TC
    gemm_body(g_hi + OFF_CTX, g_lo + OFF_CTX, g_hi + OFF_WO, g_lo + OFF_WO, out, 3, 32);
#endif
}

// ---------------- tcgen05 flash attention v6d (R14/15, proven) --------------
#define F_TM      0
#define F_KF(u)   (16 + (u) * 8)
#define F_VF(u)   (32 + (u) * 8)
#define F_SD(b)   (48 + (b) * 8)
#define F_OD(b)   (64 + (b) * 8)
#define F_QFULL   80
#define F_LRED    512               // 256 floats
#define F_QH      2048
#define F_QL      (F_QH + 16384)
#define F_KSTG    (F_QL + 16384)    // 2 x 16KB
#define F_VSTG    (F_KSTG + 32768)  // 2 x 16KB
#define FLASH_SMEM (F_VSTG + 32768) // 100352
#define TC_S(b)  ((b) * 64)
#define TC_O     128
#define TC_PH    192
#define TC_PL    224

__global__ void __launch_bounds__(256, 2)
flash_tc(const int* __restrict__ mask) {
#if HAS_TC
    extern __shared__ char fsm[];
    const uint32_t sb = smem_u32(fsm);
    const int tid = threadIdx.x;
    const int lane = tid & 31;
    const int sp = (tid >> 5) & 3;
    const int ch = tid >> 7;              // column half (32 of 64 keys)
    const int r = sp * 32 + lane;         // row 0..127
    const int bh = blockIdx.z * NHEAD + blockIdx.y;
    const int qt = blockIdx.x;

    if (tid == 0) {
        MBARRIER_INIT(sb + F_KF(0), 1);
        MBARRIER_INIT(sb + F_KF(1), 1);
        MBARRIER_INIT(sb + F_VF(0), 1);
        MBARRIER_INIT(sb + F_VF(1), 1);
        MBARRIER_INIT(sb + F_SD(0), 1);
        MBARRIER_INIT(sb + F_SD(1), 1);
        MBARRIER_INIT(sb + F_OD(0), 1);
        MBARRIER_INIT(sb + F_OD(1), 1);
        MBARRIER_INIT(sb + F_QFULL, 1);
        FENCE_PROXY_ASYNC();
    }
    if ((tid >> 5) == 0) {
        TCGEN05_ALLOC(sb + F_TM, 256);
        TCGEN05_RELINQ();   // release permit -> co-resident CTA can alloc
    }
    __syncthreads();

    uint32_t tmem;
    asm volatile("ld.shared.b32 %0, [%1];" : "=r"(tmem) : "r"(sb + F_TM));

    // tile t (0..31): 64-key half (t&1) of 128-key tile (t>>1).
    auto issue_K = [&](int t, int u) {
        const size_t koff = (((size_t)(bh * 16 + (t >> 1))) << 14) + (size_t)(t & 1) * 8192;
        const uint32_t d1 = sb + F_KSTG + u * 16384;
        MBARRIER_EXPECT_TX(sb + F_KF(u), 16384);
        BULK_G2S(d1 + 0,    (const char*)g_tkh + koff, 8192, sb + F_KF(u));
        BULK_G2S(d1 + 8192, (const char*)g_tkl + koff, 8192, sb + F_KF(u));
    };
    auto issue_V = [&](int t, int u) {
        const size_t koff = (((size_t)(bh * 16 + (t >> 1))) << 14) + (size_t)(t & 1) * 8192;
        const uint32_t d1 = sb + F_VSTG + u * 16384;
        MBARRIER_EXPECT_TX(sb + F_VF(u), 16384);
        BULK_G2S(d1 + 0,    (const char*)g_tvh + koff, 8192, sb + F_VF(u));
        BULK_G2S(d1 + 8192, (const char*)g_tvl + koff, 8192, sb + F_VF(u));
    };
    auto do_mma1 = [&](int u, int b) {   // S(b)[128,64] = Q @ K^T (3-term)
        const uint64_t dqh = MAKE_DESC(sb + F_QH);
        const uint64_t dql = MAKE_DESC(sb + F_QL);
        const uint64_t dkh = MAKE_DESC(sb + F_KSTG + u * 16384);
        const uint64_t dkl = MAKE_DESC(sb + F_KSTG + u * 16384 + 8192);
        const uint32_t sdst = tmem + TC_S(b);
        #pragma unroll
        for (int ks = 0; ks < 4; ks++)
            mma_ss(sdst, dqh + ks * 2, dkh + ks * 2, IDESC_N64, ks > 0);
        #pragma unroll
        for (int ks = 0; ks < 4; ks++)
            mma_ss(sdst, dqh + ks * 2, dkl + ks * 2, IDESC_N64, true);
        #pragma unroll
        for (int ks = 0; ks < 4; ks++)
            mma_ss(sdst, dql + ks * 2, dkh + ks * 2, IDESC_N64, true);
    };
    auto do_mma2 = [&](int u, bool first) {   // O += P @ V^T (3-term)
        const uint64_t dvh = MAKE_DESC(sb + F_VSTG + u * 16384);
        const uint64_t dvl = MAKE_DESC(sb + F_VSTG + u * 16384 + 8192);
        #pragma unroll
        for (int ks = 0; ks < 4; ks++)
            mma_ts(tmem + TC_O, tmem + TC_PH + ks * 8, dvh + ks * 2, IDESC_N64,
                   !(first && ks == 0));
        #pragma unroll
        for (int ks = 0; ks < 4; ks++)
            mma_ts(tmem + TC_O, tmem + TC_PH + ks * 8, dvl + ks * 2, IDESC_N64, true);
        #pragma unroll
        for (int ks = 0; ks < 4; ks++)
            mma_ts(tmem + TC_O, tmem + TC_PL + ks * 8, dvh + ks * 2, IDESC_N64, true);
    };

    // Preamble: Q; K0->Kstg0, K1->Kstg1, V0->Vstg0, V1->Vstg1; MMA1(0)->S0.
    if (tid == 0) {
        const size_t qoff = ((size_t)(bh * 16 + qt)) << 14;
        MBARRIER_EXPECT_TX(sb + F_QFULL, 32768);
        BULK_G2S(sb + F_QH, (const char*)g_tqh + qoff, TILE_B, sb + F_QFULL);
        BULK_G2S(sb + F_QL, (const char*)g_tql + qoff, TILE_B, sb + F_QFULL);
        issue_K(0, 0);
        issue_K(1, 1);
        issue_V(0, 0);
        issue_V(1, 1);
        MBARRIER_WAIT_PARITY(sb + F_QFULL, 0);
        MBARRIER_WAIT_PARITY(sb + F_KF(0), 0);
        do_mma1(0, 0);
        TCGEN05_COMMIT(sb + F_SD(0));
    }

    const float cs = 0.125f * 1.4426950408889634f;
    const float CB = 20.0f;
    const int* mk = mask + blockIdx.z * SEQ;
    float lsum = 0.f;

    for (int j = 0; j < 32; j++) {
        const int b = j & 1;
        const int p2 = (j >> 1) & 1;

        // Hoist mask loads (independent of S) above the SD wait.
        const int* mrow = mk + j * 64 + ch * 32;
        int4 mm0 = *reinterpret_cast<const int4*>(mrow + 0);
        int4 mm1 = *reinterpret_cast<const int4*>(mrow + 4);
        int4 mm2 = *reinterpret_cast<const int4*>(mrow + 8);
        int4 mm3 = *reinterpret_cast<const int4*>(mrow + 12);
        int4 mm4 = *reinterpret_cast<const int4*>(mrow + 16);
        int4 mm5 = *reinterpret_cast<const int4*>(mrow + 20);
        int4 mm6 = *reinterpret_cast<const int4*>(mrow + 24);
        int4 mm7 = *reinterpret_cast<const int4*>(mrow + 28);
        int mrs[32] = {mm0.x, mm0.y, mm0.z, mm0.w, mm1.x, mm1.y, mm1.z, mm1.w,
                       mm2.x, mm2.y, mm2.z, mm2.w, mm3.x, mm3.y, mm3.z, mm3.w,
                       mm4.x, mm4.y, mm4.z, mm4.w, mm5.x, mm5.y, mm5.z, mm5.w,
                       mm6.x, mm6.y, mm6.z, mm6.w, mm7.x, mm7.y, mm7.z, mm7.w};

        // tid0: MMA1(j+1) into S(b^1).
        if (tid == 0 && j + 1 <= 31) {
            MBARRIER_WAIT_PARITY(sb + F_KF((j + 1) & 1), ((j + 1) >> 1) & 1);
            do_mma1((j + 1) & 1, b ^ 1);
            TCGEN05_COMMIT(sb + F_SD(b ^ 1));
        }

        // All: wait MMA1(j) (SD(b) commit #(j>>1)).
        MBARRIER_WAIT_PARITY(sb + F_SD(b), p2);
        TCGEN05_FENCE_AFTER();

        // K refill: tile j+2 into K-stage j&1 (K(j) just consumed by MMA1(j)).
        if (tid == 0 && j + 2 <= 31) issue_K(j + 2, b);

        // Split LDTM: softmax of first 16 cols overlaps the second load.
        uint32_t ph[16], pl[16];
        float lacc = 0.f;
        uint32_t sr0[16], sr1[16];
        TCGEN05_LD_X16(sr0, tmem + TC_S(b) + ch * 32);
        TCGEN05_LD_X16(sr1, tmem + TC_S(b) + ch * 32 + 16);
        TCGEN05_WAIT_LD();
        #pragma unroll
        for (int g = 0; g < 4; g++) {
            float p0 = mrs[4 * g + 0] ? ex2f(fmaf(__uint_as_float(sr0[4 * g + 0]), cs, -CB)) : 0.f;
            float p1 = mrs[4 * g + 1] ? ex2f(fmaf(__uint_as_float(sr0[4 * g + 1]), cs, -CB)) : 0.f;
            float p2f = mrs[4 * g + 2] ? ex2f(fmaf(__uint_as_float(sr0[4 * g + 2]), cs, -CB)) : 0.f;
            float p3 = mrs[4 * g + 3] ? ex2f(fmaf(__uint_as_float(sr0[4 * g + 3]), cs, -CB)) : 0.f;
            lacc += (p0 + p1) + (p2f + p3);
            split2(p0, p1, ph[2 * g],     pl[2 * g]);
            split2(p2f, p3, ph[2 * g + 1], pl[2 * g + 1]);
        }
        #pragma unroll
        for (int g = 4; g < 8; g++) {
            float p0 = mrs[4 * g + 0] ? ex2f(fmaf(__uint_as_float(sr1[4 * g - 16]), cs, -CB)) : 0.f;
            float p1 = mrs[4 * g + 1] ? ex2f(fmaf(__uint_as_float(sr1[4 * g - 15]), cs, -CB)) : 0.f;
            float p2f = mrs[4 * g + 2] ? ex2f(fmaf(__uint_as_float(sr1[4 * g - 14]), cs, -CB)) : 0.f;
            float p3 = mrs[4 * g + 3] ? ex2f(fmaf(__uint_as_float(sr1[4 * g - 13]), cs, -CB)) : 0.f;
            lacc += (p0 + p1) + (p2f + p3);
            split2(p0, p1, ph[2 * g],     pl[2 * g]);
            split2(p2f, p3, ph[2 * g + 1], pl[2 * g + 1]);
        }
        lsum += lacc;

        // P single-buffered: MMA2(j-1) must be done before overwrite.
        if (j >= 1) {
            MBARRIER_WAIT_PARITY(sb + F_OD((j - 1) & 1), ((j - 1) >> 1) & 1);
            TCGEN05_FENCE_AFTER();
            // V refill rides the same wait: stage (j+1)&1 held V(j-1).
            if (tid == 0 && j + 1 <= 31) issue_V(j + 1, (j + 1) & 1);
        }
        TCGEN05_ST_X16(tmem + TC_PH + ch * 16, ph);
        TCGEN05_ST_X16(tmem + TC_PL + ch * 16, pl);
        TCGEN05_WAIT_ST();
        TCGEN05_FENCE_BEFORE();
        __syncthreads();

        if (tid == 0) {
            MBARRIER_WAIT_PARITY(sb + F_VF(b), p2);
            TCGEN05_FENCE_AFTER();
            do_mma2(b, j == 0);
            TCGEN05_COMMIT(sb + F_OD(b));
        }
    }

    // Epilogue: MMA2(31) is the 16th commit on OD(1) (phase 15) -> parity 1.
    MBARRIER_WAIT_PARITY(sb + F_OD(1), 1);
    TCGEN05_FENCE_AFTER();
    uint32_t od[32];
    TCGEN05_LD_X32(od, tmem + TC_O + ch * 32);
    TCGEN05_WAIT_LD();
    TCGEN05_FENCE_BEFORE();

    float* lred = (float*)(fsm + F_LRED);
    lred[ch * 128 + r] = lsum;
    __syncthreads();
    const float ltot = lsum + lred[(1 - ch) * 128 + r];
    const float inv = 1.f / ltot;

    const int h = blockIdx.y;
    const int mt_g = blockIdx.z * 16 + qt;
    char* hb = (char*)g_hi + (((size_t)OFF_CTX) << 1) + (((size_t)(h * 32 + mt_g)) << 14);
    char* lb = (char*)g_lo + (((size_t)OFF_CTX) << 1) + (((size_t)(h * 32 + mt_g)) << 14);
    #pragma unroll
    for (int c = 0; c < 32; c += 8) {
        uint4 hq, lq;
        split2(__uint_as_float(od[c + 0]) * inv, __uint_as_float(od[c + 1]) * inv, hq.x, lq.x);
        split2(__uint_as_float(od[c + 2]) * inv, __uint_as_float(od[c + 3]) * inv, hq.y, lq.y);
        split2(__uint_as_float(od[c + 4]) * inv, __uint_as_float(od[c + 5]) * inv, hq.z, lq.z);
        split2(__uint_as_float(od[c + 6]) * inv, __uint_as_float(od[c + 7]) * inv, hq.w, lq.w);
        uint32_t off = SWZ128((uint32_t)(r * 128 + (ch * 32 + c) * 2));
        *(uint4*)(hb + off) = hq;
        *(uint4*)(lb + off) = lq;
    }

    __syncthreads();
    if ((tid >> 5) == 0) {
        TCGEN05_DEALLOC(tmem, 256);
    }
#endif
}

// ---------------- Launch -----------------------------------------------------
extern "C" void kernel_launch(void* const* d_in, const int* in_sizes, int n_in,
                              void* d_out, int out_size) {
    const float* q    = (const float*)d_in[0];
    const float* k    = (const float*)d_in[1];
    const float* v    = (const float*)d_in[2];
    const int*   mask = (const int*)  d_in[3];
    const float* Wq   = (const float*)d_in[4];
    const float* Wk   = (const float*)d_in[5];
    const float* Wv   = (const float*)d_in[6];
    const float* Wo   = (const float*)d_in[7];
    float* out = (float*)d_out;

    cudaFuncSetAttribute(gemm_qkv, cudaFuncAttributeMaxDynamicSharedMemorySize, GEMM_SMEM);
    cudaFuncSetAttribute(gemm_wo, cudaFuncAttributeMaxDynamicSharedMemorySize, GEMM_SMEM);
    cudaFuncSetAttribute(flash_tc, cudaFuncAttributeMaxDynamicSharedMemorySize, FLASH_SMEM);

    dim3 conv_grid(2048, 1, 7);
    dim3 qkv_grid(8, 32, 3);      // 128x128 tiles, 768 CTAs, 2/SM
    dim3 wo_grid(8, 32);          // 256 CTAs
    dim3 fa_grid_tc(SEQ / 128, NHEAD, BATCH);

    convert_all<<<conv_grid, 256>>>(q, k, v, Wq, Wk, Wv, Wo);

    gemm_qkv<<<qkv_grid, 256, GEMM_SMEM>>>();

    flash_tc<<<fa_grid_tc, 256, FLASH_SMEM>>>(mask);

    gemm_wo<<<wo_grid, 256, GEMM_SMEM>>>(out);
}

// round 17
// speedup vs baseline: 1.1239x; 1.1239x over previous
#include <cuda_runtime.h>
#include <cuda_bf16.h>
#include <math.h>
#include <stdint.h>

// ---------------- Problem constants ----------------
#define BATCH  2
#define SEQ    2048
#define DMODEL 1024
#define NHEAD  16
#define DK     64
#define MROWS  4096        // BATCH*SEQ
#define KDIM   1024
#define KC_COUNT 16        // KDIM / 64

// Feature gate: tcgen05 exists only in the arch-specific target.
#if defined(__CUDA_ARCH_FEAT_SM103_ALL) || defined(__CUDA_ARCH_FEAT_SM100_ALL) || defined(__CUDA_ARCH_FEAT_SM101_ALL)
#define HAS_TC 1
#else
#define HAS_TC 0
#endif

// ---------------- Scratch (device globals; allocations forbidden) ----------
#define OFF_Q   0
#define OFF_K   4194304
#define OFF_V   8388608
#define OFF_CTX 12582912
#define OFF_WQ  16777216
#define OFF_WK  17825792
#define OFF_WV  18874368
#define OFF_WO  19922944
__device__ __nv_bfloat16 g_hi[20971520];
__device__ __nv_bfloat16 g_lo[20971520];

// Mask as additive exp2-bias: -CB (unmasked) or -1e9 (masked).
__device__ float g_mbias[BATCH * SEQ];

// Attention operand tiles (written by projection GEMM epilogues):
// Q,K: per (bh, stile) [128 seq x 64 dk] bf16 SW128 tiles (16KB each).
// V:   per (bh, stile) transposed [64 dk x 128 keys] blocked-atom SW128 tiles.
__device__ __align__(1024) __nv_bfloat16 g_tqh[4194304];
__device__ __align__(1024) __nv_bfloat16 g_tql[4194304];
__device__ __align__(1024) __nv_bfloat16 g_tkh[4194304];
__device__ __align__(1024) __nv_bfloat16 g_tkl[4194304];
__device__ __align__(1024) __nv_bfloat16 g_tvh[4194304];
__device__ __align__(1024) __nv_bfloat16 g_tvl[4194304];

// ---------------- PTX helpers ----------------
__device__ __forceinline__ uint32_t smem_u32(const void* p) {
    uint32_t a;
    asm("{ .reg .u64 t; cvta.to.shared.u64 t, %1; cvt.u32.u64 %0, t; }" : "=r"(a) : "l"(p));
    return a;
}

#define SWZ128(o) ((o) ^ (((o) >> 3) & 0x70))

#define MBARRIER_INIT(addr, cnt) \
    asm volatile("mbarrier.init.shared.b64 [%0], %1;" :: "r"(addr), "r"(cnt) : "memory")

#define MBARRIER_EXPECT_TX(addr, bytes) \
    asm volatile("mbarrier.arrive.expect_tx.shared.b64 _, [%0], %1;" :: "r"(addr), "r"(bytes) : "memory")

#define MBARRIER_WAIT_PARITY(addr, par) do {                                  \
    uint32_t _m = (addr); uint32_t _p = (par); uint32_t _d;                   \
    asm volatile("{\n\t.reg .pred p;\n\t"                                     \
        "mbarrier.try_wait.parity.acquire.cta.shared::cta.b64 p, [%1], %2;\n\t"\
        "selp.b32 %0, 1, 0, p;\n\t}" : "=r"(_d) : "r"(_m), "r"(_p) : "memory");\
    if (!_d) {                                                                \
        asm volatile("{\n\t.reg .pred P1;\n\t"                                \
        "W_%=:\n\t"                                                           \
        "mbarrier.try_wait.parity.acquire.cta.shared::cta.b64 P1, [%0], %1, 0x989680;\n\t" \
        "@P1 bra.uni D_%=;\n\t"                                               \
        "bra.uni W_%=;\n\t"                                                   \
        "D_%=:\n\t}" :: "r"(_m), "r"(_p) : "memory");                         \
    }                                                                         \
} while (0)

#define BULK_G2S(dst, src, bytes, mbar) \
    asm volatile("cp.async.bulk.shared::cluster.global.mbarrier::complete_tx::bytes [%0], [%1], %2, [%3];" \
        :: "r"(dst), "l"(src), "r"(bytes), "r"(mbar) : "memory")

#define TCGEN05_ALLOC(saddr, ncols) \
    asm volatile("tcgen05.alloc.cta_group::1.sync.aligned.shared::cta.b32 [%0], %1;" \
        :: "r"(saddr), "r"(ncols) : "memory")
#define TCGEN05_DEALLOC(tmem, ncols) \
    asm volatile("tcgen05.dealloc.cta_group::1.sync.aligned.b32 %0, %1;" :: "r"(tmem), "r"(ncols))
#define TCGEN05_RELINQ() \
    asm volatile("tcgen05.relinquish_alloc_permit.cta_group::1.sync.aligned;")
#define TCGEN05_COMMIT(mbar) \
    asm volatile("tcgen05.commit.cta_group::1.mbarrier::arrive::one.shared::cluster.b64 [%0];" \
        :: "r"(mbar) : "memory")
#define TCGEN05_FENCE_AFTER()  asm volatile("tcgen05.fence::after_thread_sync;" ::: "memory")
#define TCGEN05_FENCE_BEFORE() asm volatile("tcgen05.fence::before_thread_sync;" ::: "memory")
#define TCGEN05_WAIT_LD()      asm volatile("tcgen05.wait::ld.sync.aligned;" ::: "memory")
#define TCGEN05_WAIT_ST()      asm volatile("tcgen05.wait::st.sync.aligned;" ::: "memory")
#define FENCE_PROXY_ASYNC()    asm volatile("fence.proxy.async.shared::cta;" ::: "memory")

#define TCGEN05_LD_X32(r, taddr) \
    asm volatile("tcgen05.ld.sync.aligned.32x32b.x32.b32 " \
        "{%0, %1, %2, %3, %4, %5, %6, %7, %8, %9, %10, %11, %12, %13, %14, %15, " \
        " %16, %17, %18, %19, %20, %21, %22, %23, %24, %25, %26, %27, %28, %29, %30, %31}, [%32];" \
        : "=r"((r)[0]), "=r"((r)[1]), "=r"((r)[2]), "=r"((r)[3]), \
          "=r"((r)[4]), "=r"((r)[5]), "=r"((r)[6]), "=r"((r)[7]), \
          "=r"((r)[8]), "=r"((r)[9]), "=r"((r)[10]), "=r"((r)[11]), \
          "=r"((r)[12]), "=r"((r)[13]), "=r"((r)[14]), "=r"((r)[15]), \
          "=r"((r)[16]), "=r"((r)[17]), "=r"((r)[18]), "=r"((r)[19]), \
          "=r"((r)[20]), "=r"((r)[21]), "=r"((r)[22]), "=r"((r)[23]), \
          "=r"((r)[24]), "=r"((r)[25]), "=r"((r)[26]), "=r"((r)[27]), \
          "=r"((r)[28]), "=r"((r)[29]), "=r"((r)[30]), "=r"((r)[31]) \
        : "r"(taddr))

#define TCGEN05_LD_X16(r, taddr) \
    asm volatile("tcgen05.ld.sync.aligned.32x32b.x16.b32 " \
        "{%0, %1, %2, %3, %4, %5, %6, %7, %8, %9, %10, %11, %12, %13, %14, %15}, [%16];" \
        : "=r"((r)[0]), "=r"((r)[1]), "=r"((r)[2]), "=r"((r)[3]), \
          "=r"((r)[4]), "=r"((r)[5]), "=r"((r)[6]), "=r"((r)[7]), \
          "=r"((r)[8]), "=r"((r)[9]), "=r"((r)[10]), "=r"((r)[11]), \
          "=r"((r)[12]), "=r"((r)[13]), "=r"((r)[14]), "=r"((r)[15]) \
        : "r"(taddr))

#define TCGEN05_ST_X16(taddr, r) \
    asm volatile("tcgen05.st.sync.aligned.32x32b.x16.b32 [%0], " \
        "{%1, %2, %3, %4, %5, %6, %7, %8, %9, %10, %11, %12, %13, %14, %15, %16};" \
        :: "r"(taddr), \
           "r"((r)[0]), "r"((r)[1]), "r"((r)[2]), "r"((r)[3]), \
           "r"((r)[4]), "r"((r)[5]), "r"((r)[6]), "r"((r)[7]), \
           "r"((r)[8]), "r"((r)[9]), "r"((r)[10]), "r"((r)[11]), \
           "r"((r)[12]), "r"((r)[13]), "r"((r)[14]), "r"((r)[15]) \
        : "memory")

// SMEM descriptor: SW128, version=1, SBO=64, LBO=1 (K-major bf16, 128B rows)
#define SMEM_DESC_BASE ((uint64_t(2) << 61) | (uint64_t(1) << 46) | (uint64_t(64) << 32) | (uint64_t(1) << 16))
#define MAKE_DESC(a) (SMEM_DESC_BASE | ((uint64_t)((a) >> 4) & 0x3FFF))

#define IDESC_N128 0x08200490u   // M=128, N=128
#define IDESC_N64  0x08100490u   // M=128, N=64

__device__ __forceinline__ void mma_ss(uint32_t d_tmem, uint64_t a_desc, uint64_t b_desc,
                                       uint32_t idesc, bool acc) {
#if HAS_TC
    uint32_t en = acc ? 1u : 0u;
    asm volatile(
        "{\n\t.reg .pred p;\n\t"
        "setp.ne.u32 p, %4, 0;\n\t"
        "tcgen05.mma.cta_group::1.kind::f16 [%0], %1, %2, %3, p;\n\t}"
        :: "r"(d_tmem), "l"(a_desc), "l"(b_desc), "r"(idesc), "r"(en) : "memory");
#endif
}
__device__ __forceinline__ void mma_ts(uint32_t d_tmem, uint32_t a_tmem, uint64_t b_desc,
                                       uint32_t idesc, bool acc) {
#if HAS_TC
    uint32_t en = acc ? 1u : 0u;
    asm volatile(
        "{\n\t.reg .pred p;\n\t"
        "setp.ne.u32 p, %4, 0;\n\t"
        "tcgen05.mma.cta_group::1.kind::f16 [%0], [%1], %2, %3, p;\n\t}"
        :: "r"(d_tmem), "r"(a_tmem), "l"(b_desc), "r"(idesc), "r"(en) : "memory");
#endif
}

__device__ __forceinline__ float ex2f(float x) {
    float y;
    asm("ex2.approx.f32 %0, %1;" : "=f"(y) : "f"(x));
    return y;
}
// Split two fp32 into packed bf16 hi + packed bf16 residual lo (rn rounding).
__device__ __forceinline__ void split2(float x, float y, uint32_t& h, uint32_t& l) {
    asm("cvt.rn.bf16x2.f32 %0, %1, %2;" : "=r"(h) : "f"(y), "f"(x));
    float hx = __uint_as_float(h << 16);
    float hy = __uint_as_float(h & 0xffff0000u);
    asm("cvt.rn.bf16x2.f32 %0, %1, %2;" : "=r"(l) : "f"(y - hy), "f"(x - hx));
}

// ---------------- Converter: 8 elems/thread, single merged launch -----------
__device__ __forceinline__ void convert_body8(const float* __restrict__ src,
                                              __nv_bfloat16* __restrict__ hi,
                                              __nv_bfloat16* __restrict__ lo, int mtiles) {
#if HAS_TC
    int idx = blockIdx.x * 256 + threadIdx.x;   // chunk index: m*128 + ck
    int m  = idx >> 7;
    int ck = idx & 127;
    int kc = ck >> 3;
    int r  = m & 127, mt = m >> 7;
    uint32_t off = SWZ128((uint32_t)(r * 128 + (ck & 7) * 16));
    size_t base = ((size_t)(kc * mtiles + mt) << 14) + off;

    const float4* s4 = reinterpret_cast<const float4*>(src + (size_t)m * KDIM + ck * 8);
    float4 a = s4[0], b = s4[1];
    uint4 hq, lq;
    split2(a.x, a.y, hq.x, lq.x);
    split2(a.z, a.w, hq.y, lq.y);
    split2(b.x, b.y, hq.z, lq.z);
    split2(b.z, b.w, hq.w, lq.w);
    *reinterpret_cast<uint4*>(reinterpret_cast<char*>(hi) + base) = hq;
    *reinterpret_cast<uint4*>(reinterpret_cast<char*>(lo) + base) = lq;
#endif
}

__global__ void __launch_bounds__(256)
convert_all(const float* __restrict__ q, const float* __restrict__ k,
            const float* __restrict__ v, const float* __restrict__ wq,
            const float* __restrict__ wk, const float* __restrict__ wv,
            const float* __restrict__ wo, const int* __restrict__ mask) {
#if HAS_TC
    const int z = blockIdx.z;
    if (z < 3) {
        const float* src = (z == 0) ? q : (z == 1) ? k : v;
        size_t off = (z == 0) ? OFF_Q : (z == 1) ? OFF_K : OFF_V;
        convert_body8(src, g_hi + off, g_lo + off, 32);
        // z==0, first 16 blocks also build the mask bias table (4096 entries).
        if (z == 0 && blockIdx.x < 16) {
            int i = blockIdx.x * 256 + threadIdx.x;
            g_mbias[i] = mask[i] ? -20.0f : -1e9f;
        }
    } else {
        if (blockIdx.x >= 512) return;   // weights: 1024x1024 only
        const float* src = (z == 3) ? wq : (z == 4) ? wk : (z == 5) ? wv : wo;
        size_t off = (z == 3) ? OFF_WQ : (z == 4) ? OFF_WK : (z == 5) ? OFF_WV : OFF_WO;
        convert_body8(src, g_hi + off, g_lo + off, 8);
    }
#endif
}

// ---------------- tcgen05 split-bf16 GEMM (R15, proven 277.0): 128x256 ------
// 4-slot half-stage ring; chunk c: kc=c>>1, part=c&1; slot s=c&3 = A-part
// (16KB) + B-part (32KB).
#define TILE_B   16384
#define SM_CTRL  0
#define SM_FULL(s)  (16 + (s) * 8)
#define SM_EMPTY(s) (48 + (s) * 8)
#define SM_DONE  80
#define GC_SLOT_B 49152
#define SM_A(s) (1024 + (s) * GC_SLOT_B)
#define SM_B(s) (SM_A(s) + 16384)
#define GEMM_SMEM (1024 + 4 * GC_SLOT_B)   // 197632

__device__ __forceinline__ void
gemm_body(const __nv_bfloat16* __restrict__ ahi, const __nv_bfloat16* __restrict__ alo,
          const __nv_bfloat16* __restrict__ bhi, const __nv_bfloat16* __restrict__ blo,
          float* __restrict__ outflat, int dst, int mtilesA) {
#if HAS_TC
    extern __shared__ char smem[];
    const uint32_t sb = smem_u32(smem);
    const int tid = threadIdx.x, wid = tid >> 5, lid = tid & 31;
    const int mt = blockIdx.y, nt = blockIdx.x;

    if (tid == 0) {
        #pragma unroll
        for (int s = 0; s < 4; s++) {
            MBARRIER_INIT(sb + SM_FULL(s), 1);
            MBARRIER_INIT(sb + SM_EMPTY(s), 1);
        }
        MBARRIER_INIT(sb + SM_DONE, 1);
        FENCE_PROXY_ASYNC();
    }
    if (wid == 0) {
        TCGEN05_ALLOC(sb + SM_CTRL, 256);
        TCGEN05_RELINQ();
    }
    __syncthreads();

    uint32_t tmem;
    asm volatile("ld.shared.b32 %0, [%1];" : "=r"(tmem) : "r"(sb + SM_CTRL));

    if (tid == 32) {
        int ph[4] = {1, 1, 1, 1};
        for (int c = 0; c < 32; c++) {
            const int s = c & 3, kc = c >> 1, part = c & 1;
            MBARRIER_WAIT_PARITY(sb + SM_EMPTY(s), ph[s]); ph[s] ^= 1;
            MBARRIER_EXPECT_TX(sb + SM_FULL(s), 3 * TILE_B);
            const char* asrc = (const char*)(part ? alo : ahi) +
                               ((size_t)(kc * mtilesA + mt) << 14);
            const char* bsrc = (const char*)(part ? blo : bhi) +
                               ((size_t)(kc * 8 + nt * 2) << 14);
            BULK_G2S(sb + SM_A(s), asrc, TILE_B, sb + SM_FULL(s));
            BULK_G2S(sb + SM_B(s), bsrc, 2 * TILE_B, sb + SM_FULL(s));
        }
    } else if (tid == 0) {
        for (int c = 0; c < 32; c++) {
            const int s = c & 3;
            MBARRIER_WAIT_PARITY(sb + SM_FULL(s), (c >> 2) & 1);
            if ((c & 1) == 0) {
                const uint64_t dah = MAKE_DESC(sb + SM_A(s));
                const uint64_t dbh = MAKE_DESC(sb + SM_B(s));
                #pragma unroll
                for (int ks = 0; ks < 4; ks++)
                    #pragma unroll
                    for (int nh = 0; nh < 2; nh++)
                        mma_ss(tmem + nh * 128, dah + ks * 2, dbh + nh * 1024 + ks * 2,
                               IDESC_N128, !(c == 0 && ks == 0));
            } else {
                const int sh = (c - 1) & 3;
                const uint64_t dah = MAKE_DESC(sb + SM_A(sh));
                const uint64_t dbh = MAKE_DESC(sb + SM_B(sh));
                const uint64_t dal = MAKE_DESC(sb + SM_A(s));
                const uint64_t dbl = MAKE_DESC(sb + SM_B(s));
                #pragma unroll
                for (int ks = 0; ks < 4; ks++)
                    #pragma unroll
                    for (int nh = 0; nh < 2; nh++) {
                        const uint32_t dd = tmem + nh * 128;
                        const uint64_t bo = nh * 1024 + ks * 2;
                        mma_ss(dd, dah + ks * 2, dbl + bo, IDESC_N128, true);
                        mma_ss(dd, dal + ks * 2, dbh + bo, IDESC_N128, true);
                    }
                TCGEN05_COMMIT(sb + SM_EMPTY(sh));
                TCGEN05_COMMIT(sb + SM_EMPTY(s));
            }
        }
        TCGEN05_COMMIT(sb + SM_DONE);
    }

    MBARRIER_WAIT_PARITY(sb + SM_DONE, 0);
    TCGEN05_FENCE_AFTER();

    const int m = mt * 128 + (wid & 3) * 32 + lid;
    #pragma unroll
    for (int chunk = 0; chunk < 2; chunk++) {
        const int colbase = (wid >> 2) * 128 + chunk * 64;
        uint32_t d[64];
        TCGEN05_LD_X32(d, tmem + colbase);
        TCGEN05_LD_X32(d + 32, tmem + colbase + 32);
        TCGEN05_WAIT_LD();

        const int ng = nt * 256 + colbase;

        if (dst < 3) {
            const int b = m >> 11, sq = m & (SEQ - 1);
            const int h = ng >> 6;
            const int tile = (b * NHEAD + h) * 16 + (sq >> 7);
            const int rr = sq & 127;
            if (dst == 0 || dst == 1) {
                char* hb = (char*)(dst == 0 ? g_tqh : g_tkh) + ((size_t)tile << 14);
                char* lb = (char*)(dst == 0 ? g_tql : g_tkl) + ((size_t)tile << 14);
                #pragma unroll
                for (int c = 0; c < 64; c += 8) {
                    uint4 hq, lq;
                    split2(__uint_as_float(d[c + 0]), __uint_as_float(d[c + 1]), hq.x, lq.x);
                    split2(__uint_as_float(d[c + 2]), __uint_as_float(d[c + 3]), hq.y, lq.y);
                    split2(__uint_as_float(d[c + 4]), __uint_as_float(d[c + 5]), hq.z, lq.z);
                    split2(__uint_as_float(d[c + 6]), __uint_as_float(d[c + 7]), hq.w, lq.w);
                    uint32_t off = SWZ128((uint32_t)(rr * 128 + c * 2));
                    *(uint4*)(hb + off) = hq;
                    *(uint4*)(lb + off) = lq;
                }
            } else {
                char* hb = (char*)g_tvh + ((size_t)tile << 14);
                char* lb = (char*)g_tvl + ((size_t)tile << 14);
                const int kin = rr;
                #pragma unroll
                for (int c = 0; c < 64; c++) {
                    float v0 = __uint_as_float(d[c]);
                    __nv_bfloat16 h0 = __float2bfloat16(v0);
                    __nv_bfloat16 l0 = __float2bfloat16(v0 - __bfloat162float(h0));
                    uint32_t bo = (uint32_t)(((c >> 3) + (kin >> 6) * 8) * 1024 +
                                             (c & 7) * 128 + (kin & 63) * 2);
                    uint32_t off = SWZ128(bo);
                    *(__nv_bfloat16*)(hb + off) = h0;
                    *(__nv_bfloat16*)(lb + off) = l0;
                }
            }
        } else {
            float* row = outflat + (size_t)m * DMODEL + ng;
            #pragma unroll
            for (int c = 0; c < 64; c += 4) {
                float4 v = make_float4(__uint_as_float(d[c]), __uint_as_float(d[c + 1]),
                                       __uint_as_float(d[c + 2]), __uint_as_float(d[c + 3]));
                *reinterpret_cast<float4*>(row + c) = v;
            }
        }
    }
    TCGEN05_FENCE_BEFORE();

    __syncthreads();
    if (wid == 0) {
        TCGEN05_DEALLOC(tmem, 256);
    }
#endif
}

__global__ void __launch_bounds__(256) gemm_qkv() {
#if HAS_TC
    const int z = blockIdx.z;
    const size_t aoff = (z == 0) ? OFF_Q : (z == 1) ? OFF_K : OFF_V;
    const size_t boff = (z == 0) ? OFF_WQ : (z == 1) ? OFF_WK : OFF_WV;
    gemm_body(g_hi + aoff, g_lo + aoff, g_hi + boff, g_lo + boff, nullptr, z, 32);
#endif
}

__global__ void __launch_bounds__(256) gemm_wo(float* __restrict__ out) {
#if HAS_TC
    gemm_body(g_hi + OFF_CTX, g_lo + OFF_CTX, g_hi + OFF_WO, g_lo + OFF_WO, out, 3, 32);
#endif
}

// ---------------- tcgen05 flash attention v6e: maskbias ----------------------
// R14/15 structure (proven) with the mask select replaced by a precomputed
// additive exp2-bias: p = ex2(fma(s, cs, bias[k])), bias = -CB or -1e9.
#define F_TM      0
#define F_KF(u)   (16 + (u) * 8)
#define F_VF(u)   (32 + (u) * 8)
#define F_SD(b)   (48 + (b) * 8)
#define F_OD(b)   (64 + (b) * 8)
#define F_QFULL   80
#define F_LRED    512               // 256 floats
#define F_QH      2048
#define F_QL      (F_QH + 16384)
#define F_KSTG    (F_QL + 16384)    // 2 x 16KB
#define F_VSTG    (F_KSTG + 32768)  // 2 x 16KB
#define FLASH_SMEM (F_VSTG + 32768) // 100352
#define TC_S(b)  ((b) * 64)
#define TC_O     128
#define TC_PH    192
#define TC_PL    224

__global__ void __launch_bounds__(256, 2)
flash_tc() {
#if HAS_TC
    extern __shared__ char fsm[];
    const uint32_t sb = smem_u32(fsm);
    const int tid = threadIdx.x;
    const int lane = tid & 31;
    const int sp = (tid >> 5) & 3;
    const int ch = tid >> 7;              // column half (32 of 64 keys)
    const int r = sp * 32 + lane;         // row 0..127
    const int bh = blockIdx.z * NHEAD + blockIdx.y;
    const int qt = blockIdx.x;

    if (tid == 0) {
        MBARRIER_INIT(sb + F_KF(0), 1);
        MBARRIER_INIT(sb + F_KF(1), 1);
        MBARRIER_INIT(sb + F_VF(0), 1);
        MBARRIER_INIT(sb + F_VF(1), 1);
        MBARRIER_INIT(sb + F_SD(0), 1);
        MBARRIER_INIT(sb + F_SD(1), 1);
        MBARRIER_INIT(sb + F_OD(0), 1);
        MBARRIER_INIT(sb + F_OD(1), 1);
        MBARRIER_INIT(sb + F_QFULL, 1);
        FENCE_PROXY_ASYNC();
    }
    if ((tid >> 5) == 0) {
        TCGEN05_ALLOC(sb + F_TM, 256);
        TCGEN05_RELINQ();
    }
    __syncthreads();

    uint32_t tmem;
    asm volatile("ld.shared.b32 %0, [%1];" : "=r"(tmem) : "r"(sb + F_TM));

    auto issue_K = [&](int t, int u) {
        const size_t koff = (((size_t)(bh * 16 + (t >> 1))) << 14) + (size_t)(t & 1) * 8192;
        const uint32_t d1 = sb + F_KSTG + u * 16384;
        MBARRIER_EXPECT_TX(sb + F_KF(u), 16384);
        BULK_G2S(d1 + 0,    (const char*)g_tkh + koff, 8192, sb + F_KF(u));
        BULK_G2S(d1 + 8192, (const char*)g_tkl + koff, 8192, sb + F_KF(u));
    };
    auto issue_V = [&](int t, int u) {
        const size_t koff = (((size_t)(bh * 16 + (t >> 1))) << 14) + (size_t)(t & 1) * 8192;
        const uint32_t d1 = sb + F_VSTG + u * 16384;
        MBARRIER_EXPECT_TX(sb + F_VF(u), 16384);
        BULK_G2S(d1 + 0,    (const char*)g_tvh + koff, 8192, sb + F_VF(u));
        BULK_G2S(d1 + 8192, (const char*)g_tvl + koff, 8192, sb + F_VF(u));
    };
    auto do_mma1 = [&](int u, int b) {
        const uint64_t dqh = MAKE_DESC(sb + F_QH);
        const uint64_t dql = MAKE_DESC(sb + F_QL);
        const uint64_t dkh = MAKE_DESC(sb + F_KSTG + u * 16384);
        const uint64_t dkl = MAKE_DESC(sb + F_KSTG + u * 16384 + 8192);
        const uint32_t sdst = tmem + TC_S(b);
        #pragma unroll
        for (int ks = 0; ks < 4; ks++)
            mma_ss(sdst, dqh + ks * 2, dkh + ks * 2, IDESC_N64, ks > 0);
        #pragma unroll
        for (int ks = 0; ks < 4; ks++)
            mma_ss(sdst, dqh + ks * 2, dkl + ks * 2, IDESC_N64, true);
        #pragma unroll
        for (int ks = 0; ks < 4; ks++)
            mma_ss(sdst, dql + ks * 2, dkh + ks * 2, IDESC_N64, true);
    };
    auto do_mma2 = [&](int u, bool first) {
        const uint64_t dvh = MAKE_DESC(sb + F_VSTG + u * 16384);
        const uint64_t dvl = MAKE_DESC(sb + F_VSTG + u * 16384 + 8192);
        #pragma unroll
        for (int ks = 0; ks < 4; ks++)
            mma_ts(tmem + TC_O, tmem + TC_PH + ks * 8, dvh + ks * 2, IDESC_N64,
                   !(first && ks == 0));
        #pragma unroll
        for (int ks = 0; ks < 4; ks++)
            mma_ts(tmem + TC_O, tmem + TC_PH + ks * 8, dvl + ks * 2, IDESC_N64, true);
        #pragma unroll
        for (int ks = 0; ks < 4; ks++)
            mma_ts(tmem + TC_O, tmem + TC_PL + ks * 8, dvh + ks * 2, IDESC_N64, true);
    };

    if (tid == 0) {
        const size_t qoff = ((size_t)(bh * 16 + qt)) << 14;
        MBARRIER_EXPECT_TX(sb + F_QFULL, 32768);
        BULK_G2S(sb + F_QH, (const char*)g_tqh + qoff, TILE_B, sb + F_QFULL);
        BULK_G2S(sb + F_QL, (const char*)g_tql + qoff, TILE_B, sb + F_QFULL);
        issue_K(0, 0);
        issue_K(1, 1);
        issue_V(0, 0);
        issue_V(1, 1);
        MBARRIER_WAIT_PARITY(sb + F_QFULL, 0);
        MBARRIER_WAIT_PARITY(sb + F_KF(0), 0);
        do_mma1(0, 0);
        TCGEN05_COMMIT(sb + F_SD(0));
    }

    const float cs = 0.125f * 1.4426950408889634f;
    const float* mb = g_mbias + blockIdx.z * SEQ;
    float lsum = 0.f;

    for (int j = 0; j < 32; j++) {
        const int b = j & 1;
        const int p2 = (j >> 1) & 1;

        // Hoist bias loads (independent of S) above the SD wait.
        const float* brow = mb + j * 64 + ch * 32;
        float4 bb0 = *reinterpret_cast<const float4*>(brow + 0);
        float4 bb1 = *reinterpret_cast<const float4*>(brow + 4);
        float4 bb2 = *reinterpret_cast<const float4*>(brow + 8);
        float4 bb3 = *reinterpret_cast<const float4*>(brow + 12);
        float4 bb4 = *reinterpret_cast<const float4*>(brow + 16);
        float4 bb5 = *reinterpret_cast<const float4*>(brow + 20);
        float4 bb6 = *reinterpret_cast<const float4*>(brow + 24);
        float4 bb7 = *reinterpret_cast<const float4*>(brow + 28);
        float bias[32] = {bb0.x, bb0.y, bb0.z, bb0.w, bb1.x, bb1.y, bb1.z, bb1.w,
                          bb2.x, bb2.y, bb2.z, bb2.w, bb3.x, bb3.y, bb3.z, bb3.w,
                          bb4.x, bb4.y, bb4.z, bb4.w, bb5.x, bb5.y, bb5.z, bb5.w,
                          bb6.x, bb6.y, bb6.z, bb6.w, bb7.x, bb7.y, bb7.z, bb7.w};

        // tid0: MMA1(j+1) into S(b^1).
        if (tid == 0 && j + 1 <= 31) {
            MBARRIER_WAIT_PARITY(sb + F_KF((j + 1) & 1), ((j + 1) >> 1) & 1);
            do_mma1((j + 1) & 1, b ^ 1);
            TCGEN05_COMMIT(sb + F_SD(b ^ 1));
        }

        // All: wait MMA1(j).
        MBARRIER_WAIT_PARITY(sb + F_SD(b), p2);
        TCGEN05_FENCE_AFTER();

        // K refill: tile j+2 into K-stage j&1.
        if (tid == 0 && j + 2 <= 31) issue_K(j + 2, b);

        uint32_t ph[16], pl[16];
        float lacc = 0.f;
        uint32_t sr0[16], sr1[16];
        TCGEN05_LD_X16(sr0, tmem + TC_S(b) + ch * 32);
        TCGEN05_LD_X16(sr1, tmem + TC_S(b) + ch * 32 + 16);
        TCGEN05_WAIT_LD();
        #pragma unroll
        for (int g = 0; g < 4; g++) {
            float p0 = ex2f(fmaf(__uint_as_float(sr0[4 * g + 0]), cs, bias[4 * g + 0]));
            float p1 = ex2f(fmaf(__uint_as_float(sr0[4 * g + 1]), cs, bias[4 * g + 1]));
            float p2f = ex2f(fmaf(__uint_as_float(sr0[4 * g + 2]), cs, bias[4 * g + 2]));
            float p3 = ex2f(fmaf(__uint_as_float(sr0[4 * g + 3]), cs, bias[4 * g + 3]));
            lacc += (p0 + p1) + (p2f + p3);
            split2(p0, p1, ph[2 * g],     pl[2 * g]);
            split2(p2f, p3, ph[2 * g + 1], pl[2 * g + 1]);
        }
        #pragma unroll
        for (int g = 4; g < 8; g++) {
            float p0 = ex2f(fmaf(__uint_as_float(sr1[4 * g - 16]), cs, bias[4 * g + 0]));
            float p1 = ex2f(fmaf(__uint_as_float(sr1[4 * g - 15]), cs, bias[4 * g + 1]));
            float p2f = ex2f(fmaf(__uint_as_float(sr1[4 * g - 14]), cs, bias[4 * g + 2]));
            float p3 = ex2f(fmaf(__uint_as_float(sr1[4 * g - 13]), cs, bias[4 * g + 3]));
            lacc += (p0 + p1) + (p2f + p3);
            split2(p0, p1, ph[2 * g],     pl[2 * g]);
            split2(p2f, p3, ph[2 * g + 1], pl[2 * g + 1]);
        }
        lsum += lacc;

        // P single-buffered: MMA2(j-1) must be done before overwrite.
        if (j >= 1) {
            MBARRIER_WAIT_PARITY(sb + F_OD((j - 1) & 1), ((j - 1) >> 1) & 1);
            TCGEN05_FENCE_AFTER();
            if (tid == 0 && j + 1 <= 31) issue_V(j + 1, (j + 1) & 1);
        }
        TCGEN05_ST_X16(tmem + TC_PH + ch * 16, ph);
        TCGEN05_ST_X16(tmem + TC_PL + ch * 16, pl);
        TCGEN05_WAIT_ST();
        TCGEN05_FENCE_BEFORE();
        __syncthreads();

        if (tid == 0) {
            MBARRIER_WAIT_PARITY(sb + F_VF(b), p2);
            TCGEN05_FENCE_AFTER();
            do_mma2(b, j == 0);
            TCGEN05_COMMIT(sb + F_OD(b));
        }
    }

    // Epilogue: MMA2(31) is the 16th commit on OD(1) -> parity 1.
    MBARRIER_WAIT_PARITY(sb + F_OD(1), 1);
    TCGEN05_FENCE_AFTER();
    uint32_t od[32];
    TCGEN05_LD_X32(od, tmem + TC_O + ch * 32);
    TCGEN05_WAIT_LD();
    TCGEN05_FENCE_BEFORE();

    float* lred = (float*)(fsm + F_LRED);
    lred[ch * 128 + r] = lsum;
    __syncthreads();
    const float ltot = lsum + lred[(1 - ch) * 128 + r];
    const float inv = 1.f / ltot;

    const int h = blockIdx.y;
    const int mt_g = blockIdx.z * 16 + qt;
    char* hb = (char*)g_hi + (((size_t)OFF_CTX) << 1) + (((size_t)(h * 32 + mt_g)) << 14);
    char* lb = (char*)g_lo + (((size_t)OFF_CTX) << 1) + (((size_t)(h * 32 + mt_g)) << 14);
    #pragma unroll
    for (int c = 0; c < 32; c += 8) {
        uint4 hq, lq;
        split2(__uint_as_float(od[c + 0]) * inv, __uint_as_float(od[c + 1]) * inv, hq.x, lq.x);
        split2(__uint_as_float(od[c + 2]) * inv, __uint_as_float(od[c + 3]) * inv, hq.y, lq.y);
        split2(__uint_as_float(od[c + 4]) * inv, __uint_as_float(od[c + 5]) * inv, hq.z, lq.z);
        split2(__uint_as_float(od[c + 6]) * inv, __uint_as_float(od[c + 7]) * inv, hq.w, lq.w);
        uint32_t off = SWZ128((uint32_t)(r * 128 + (ch * 32 + c) * 2));
        *(uint4*)(hb + off) = hq;
        *(uint4*)(lb + off) = lq;
    }

    __syncthreads();
    if ((tid >> 5) == 0) {
        TCGEN05_DEALLOC(tmem, 256);
    }
#endif
}

// ---------------- Launch -----------------------------------------------------
extern "C" void kernel_launch(void* const* d_in, const int* in_sizes, int n_in,
                              void* d_out, int out_size) {
    const float* q    = (const float*)d_in[0];
    const float* k    = (const float*)d_in[1];
    const float* v    = (const float*)d_in[2];
    const int*   mask = (const int*)  d_in[3];
    const float* Wq   = (const float*)d_in[4];
    const float* Wk   = (const float*)d_in[5];
    const float* Wv   = (const float*)d_in[6];
    const float* Wo   = (const float*)d_in[7];
    float* out = (float*)d_out;

    cudaFuncSetAttribute(gemm_qkv, cudaFuncAttributeMaxDynamicSharedMemorySize, GEMM_SMEM);
    cudaFuncSetAttribute(gemm_wo, cudaFuncAttributeMaxDynamicSharedMemorySize, GEMM_SMEM);
    cudaFuncSetAttribute(flash_tc, cudaFuncAttributeMaxDynamicSharedMemorySize, FLASH_SMEM);

    dim3 conv_grid(2048, 1, 7);
    dim3 qkv_grid(4, 32, 3);      // 128x256 tiles (R15 proven)
    dim3 wo_grid(4, 32);
    dim3 fa_grid_tc(SEQ / 128, NHEAD, BATCH);

    convert_all<<<conv_grid, 256>>>(q, k, v, Wq, Wk, Wv, Wo, mask);

    gemm_qkv<<<qkv_grid, 256, GEMM_SMEM>>>();

    flash_tc<<<fa_grid_tc, 256, FLASH_SMEM>>>();

    gemm_wo<<<wo_grid, 256, GEMM_SMEM>>>(out);
}